// round 6
// baseline (speedup 1.0000x reference)
#include <cuda_runtime.h>
#include <math.h>

#define TT    512
#define DPOI  256
#define DIN   260
#define DHID  356
#define G3    1536
#define HH    512
#define CL    16          // cluster size
#define DPC   32          // h-dims per CTA
#define RPC   96          // rows per CTA
#define HSTR  33          // hist stride (bank-conflict pad)

__device__ float g_x  [TT * DPOI];
__device__ float g_hid[TT * DHID];
__device__ float g_gi [TT * G3];

__device__ __forceinline__ float warp_sum(float v) {
#pragma unroll
    for (int o = 16; o > 0; o >>= 1) v += __shfl_xor_sync(0xffffffffu, v, o);
    return v;
}
__device__ __forceinline__ unsigned smem_u32(const void* p) {
    unsigned a;
    asm("{ .reg .u64 t; cvta.to.shared.u64 t, %1; cvt.u32.u64 %0, t; }" : "=r"(a) : "l"(p));
    return a;
}
__device__ __forceinline__ void st_dsmem(unsigned addr, unsigned rank, float v) {
    unsigned ra;
    asm volatile("mapa.shared::cluster.u32 %0, %1, %2;" : "=r"(ra) : "r"(addr), "r"(rank));
    asm volatile("st.shared::cluster.f32 [%0], %1;" :: "r"(ra), "f"(v) : "memory");
}
__device__ __forceinline__ void cluster_sync_() {
    asm volatile("barrier.cluster.arrive.aligned;" ::: "memory");
    asm volatile("barrier.cluster.wait.aligned;"   ::: "memory");
}
__device__ __forceinline__ void mbar_init(unsigned a, unsigned cnt) {
    asm volatile("mbarrier.init.shared.b64 [%0], %1;" :: "r"(a), "r"(cnt) : "memory");
}
__device__ __forceinline__ void mbar_expect(unsigned a, unsigned tx) {
    asm volatile("mbarrier.arrive.expect_tx.shared.b64 _, [%0], %1;" :: "r"(a), "r"(tx) : "memory");
}
__device__ __forceinline__ void mbar_wait(unsigned a, unsigned parity) {
    unsigned done;
    asm volatile(
        "{\n\t.reg .pred p;\n\t"
        "mbarrier.try_wait.parity.acquire.cta.shared::cta.b64 p, [%1], %2;\n\t"
        "selp.b32 %0, 1, 0, p;\n\t}"
        : "=r"(done) : "r"(a), "r"(parity) : "memory");
    if (!done) {
        asm volatile(
            "{\n\t.reg .pred P1;\n\t"
            "W_%=:\n\t"
            "mbarrier.try_wait.parity.acquire.cta.shared::cta.b64 P1, [%0], %1;\n\t"
            "@P1 bra.uni D_%=;\n\t"
            "bra.uni W_%=;\n\t"
            "D_%=:\n\t}"
            :: "r"(a), "r"(parity) : "memory");
    }
}
__device__ __forceinline__ void st_async_f32(unsigned dst, unsigned bar, unsigned rk, float v) {
    unsigned rd, rb;
    asm volatile("mapa.shared::cluster.u32 %0, %1, %2;" : "=r"(rd) : "r"(dst), "r"(rk));
    asm volatile("mapa.shared::cluster.u32 %0, %1, %2;" : "=r"(rb) : "r"(bar), "r"(rk));
    asm volatile("st.async.shared::cluster.mbarrier::complete_tx::bytes.b32 [%0], %1, [%2];"
                 :: "r"(rd), "r"(__float_as_uint(v)), "r"(rb) : "memory");
}
__device__ __forceinline__ float fast_sig(float x) {
    return __fdividef(1.f, 1.f + __expf(-x));
}
__device__ __forceinline__ float fast_tanh(float x) {
    return 2.f * __fdividef(1.f, 1.f + __expf(-2.f * x)) - 1.f;
}

// ---------------------------------------------------------------- K1a: gather+feat+LN + W1/GELU
// grid (64, 2): 8 timesteps x half of D_HID per CTA.
__global__ __launch_bounds__(256) void k1a(
    const int* __restrict__ idx, const float* __restrict__ tf,
    const float* __restrict__ emb, const float* __restrict__ ll,
    const float* __restrict__ lnw, const float* __restrict__ lnb,
    const float* __restrict__ w1, const float* __restrict__ b1)
{
    __shared__ float xs[8 * DIN];
    const int tid = threadIdx.x, warp = tid >> 5, lane = tid & 31;
    const int t0 = blockIdx.x * 8;
    const int hbase = blockIdx.y * 178;

    {   // one warp per timestep: gather + features + LayerNorm
        const int t = t0 + warp;
        const int pid = idx[t];
        const float4* er = (const float4*)(emb + (size_t)pid * DPOI);
        *(float4*)(xs + warp * DIN + 4 * lane)       = er[lane];
        *(float4*)(xs + warp * DIN + 128 + 4 * lane) = er[lane + 32];
        if (lane == 0) {
            float tc = fminf(fmaxf(tf[t], 0.f), 1.f);
            float s, c; sincosf(6.283185307179586f * tc, &s, &c);
            float f2 = 0.f, f3 = 0.f;
            if (t > 0) {
                float tp = fminf(fmaxf(tf[t - 1], 0.f), 1.f);
                float d = tc - tp;
                float m = d - floorf(d);
                f2 = log1pf(m * 24.f);
                const int ia = idx[t - 1];
                const float R = 0.017453292519943295f;
                float la1 = R * fminf(fmaxf(ll[2 * ia  + 0],  -90.f),  90.f);
                float lo1 = R * fminf(fmaxf(ll[2 * ia  + 1], -180.f), 180.f);
                float la2 = R * fminf(fmaxf(ll[2 * pid + 0],  -90.f),  90.f);
                float lo2 = R * fminf(fmaxf(ll[2 * pid + 1], -180.f), 180.f);
                float sa = sinf((la2 - la1) * 0.5f);
                float sb = sinf((lo2 - lo1) * 0.5f);
                float a = sa * sa + cosf(la1) * cosf(la2) * sb * sb;
                a = fminf(fmaxf(a, 0.f), 1.f);
                float cc = 2.f * atan2f(sqrtf(a), sqrtf(fmaxf(1.f - a, 1e-12f)));
                f3 = log1pf(6371.0088f * cc);
            }
            xs[warp * DIN + 256] = s;  xs[warp * DIN + 257] = c;
            xs[warp * DIN + 258] = f2; xs[warp * DIN + 259] = f3;
        }
        __syncwarp();
        float sm = 0.f, s2 = 0.f;
        for (int k = lane; k < DIN; k += 32) { float v = xs[warp * DIN + k]; sm += v; s2 += v * v; }
        sm = warp_sum(sm); s2 = warp_sum(s2);
        const float mu = sm * (1.f / DIN);
        const float inv = rsqrtf(s2 * (1.f / DIN) - mu * mu + 1e-5f);
        for (int k = lane; k < DIN; k += 32) {
            float v = xs[warp * DIN + k];
            xs[warp * DIN + k] = (v - mu) * inv * __ldg(&lnw[k]) + __ldg(&lnb[k]);
        }
    }
    __syncthreads();

    if (tid < 178) {
        const int h = hbase + tid;
        float acc[8];
#pragma unroll
        for (int i = 0; i < 8; i++) acc[i] = 0.f;
#pragma unroll 4
        for (int k = 0; k < DIN; k++) {
            const float wv = __ldg(&w1[k * DHID + h]);
#pragma unroll
            for (int i = 0; i < 8; i++) acc[i] = fmaf(xs[i * DIN + k], wv, acc[i]);
        }
        const float bb = __ldg(&b1[h]);
#pragma unroll
        for (int i = 0; i < 8; i++) {
            float v = acc[i] + bb;
            g_hid[(t0 + i) * DHID + h] = 0.5f * v * (1.f + erff(v * 0.7071067811865475f));
        }
    }
}

// ---------------------------------------------------------------- K1b: x = hid @ W2 + b2
__global__ __launch_bounds__(256) void k1b(
    const float* __restrict__ w2, const float* __restrict__ b2)
{
    __shared__ float hb[8 * DHID];
    const int tid = threadIdx.x;
    const int t0 = blockIdx.x * 8;

    for (int i = tid; i < 8 * DHID; i += 256) hb[i] = g_hid[t0 * DHID + i];
    __syncthreads();

    float acc[8];
#pragma unroll
    for (int i = 0; i < 8; i++) acc[i] = 0.f;
#pragma unroll 4
    for (int k = 0; k < DHID; k++) {
        const float wv = __ldg(&w2[k * DPOI + tid]);
#pragma unroll
        for (int i = 0; i < 8; i++) acc[i] = fmaf(hb[i * DHID + k], wv, acc[i]);
    }
    const float bo = __ldg(&b2[tid]);
#pragma unroll
    for (int i = 0; i < 8; i++) g_x[(t0 + i) * DPOI + tid] = acc[i] + bo;
}

// ---------------------------------------------------------------- K2: gi = x @ W_ih^T + b_ih
__global__ __launch_bounds__(256) void k2_gi(
    const float* __restrict__ wih, const float* __restrict__ bih)
{
    __shared__ float xsm[8 * DPOI];
    __shared__ float wsmT[16 * 257];
    const int tid = threadIdx.x;
    const int t0 = blockIdx.x * 8;
    const int g0 = blockIdx.y * 256;

    for (int i = tid; i < 8 * DPOI; i += 256) xsm[i] = g_x[t0 * DPOI + i];

    float acc[8];
#pragma unroll
    for (int i = 0; i < 8; i++) acc[i] = 0.f;

    for (int k0 = 0; k0 < DPOI; k0 += 16) {
        __syncthreads();
        for (int i = tid; i < 4096; i += 256) {
            const int kk = i & 15, g = i >> 4;
            wsmT[kk * 257 + g] = wih[(size_t)(g0 + g) * DPOI + k0 + kk];
        }
        __syncthreads();
#pragma unroll
        for (int k4 = 0; k4 < 4; k4++) {
            float4 xv[8];
#pragma unroll
            for (int i = 0; i < 8; i++) xv[i] = *(const float4*)(xsm + i * DPOI + k0 + 4 * k4);
#pragma unroll
            for (int c = 0; c < 4; c++) {
                const float w = wsmT[(4 * k4 + c) * 257 + tid];
#pragma unroll
                for (int i = 0; i < 8; i++) {
                    float xk = (c == 0) ? xv[i].x : (c == 1) ? xv[i].y : (c == 2) ? xv[i].z : xv[i].w;
                    acc[i] = fmaf(xk, w, acc[i]);
                }
            }
        }
    }
    const float b = __ldg(&bih[g0 + tid]);
#pragma unroll
    for (int i = 0; i < 8; i++) g_gi[(size_t)(t0 + i) * G3 + g0 + tid] = acc[i] + b;
}

// ---------------------------------------------------------------- K3: GRU scan + fused epilogue
// 16-CTA cluster, 4-slot mbarrier pipeline, all-warp-local gating.
// Warp w owns dims {2w, 2w+1}; its 6 W_hh rows live in registers (f32x2).
__global__ void __launch_bounds__(512, 1) __cluster_dims__(CL, 1, 1)
k3_gru(const float* __restrict__ whh, const float* __restrict__ bhh,
       const float* __restrict__ gq, const float* __restrict__ loglam,
       float* __restrict__ out, int out_size)
{
    extern __shared__ float sm[];
    float* hbuf = sm;                    // 4*512          [0,2048)
    float* hist = sm + 2048;             // 512*33         [2048,18944)
    float* part = sm + 18944;            // 16*512         [18944,27136)
    float* attn = sm + 27136;            // 512
    float* scp  = sm + 27648;            // 512
    float* qv   = sm + 28160;            // 32
    float* red  = sm + 28192;            // 16
    const unsigned mb = smem_u32(sm + 28208);   // 4 mbarriers (8B each)
#define MB_FULL(s) (mb + (unsigned)((s) * 8))

    const int tid = threadIdx.x, warp = tid >> 5, lane = tid & 31;
    unsigned c; asm("mov.u32 %0, %%cluster_ctarank;" : "=r"(c));

    if (tid == 0) {
#pragma unroll
        for (int s = 0; s < 4; s++) mbar_init(MB_FULL(s), 1);
    }
    for (int i = tid; i < 2048; i += 512) hbuf[i] = 0.f;
    if (tid < 32) qv[tid] = gq[(int)c * DPC + tid] * rsqrtf((float)HH);

    // per-warp resident rows: r = 0..5 -> gate (r>>1), local dim 2*warp + (r&1)
    unsigned long long w[6][8];
#pragma unroll
    for (int r = 0; r < 6; r++) {
        const int grow = (r >> 1) * HH + (int)c * DPC + 2 * warp + (r & 1);
        const unsigned long long* wp = (const unsigned long long*)(whh + (size_t)grow * HH);
#pragma unroll
        for (int j = 0; j < 8; j++) w[r][j] = wp[lane + 32 * j];
    }
    // lanes 0,1: own-dim state
    const int d = 2 * warp + (lane & 1);
    float b_r = 0.f, b_z = 0.f, b_n = 0.f, gi_r = 0.f, gi_z = 0.f, gi_n = 0.f;
    if (lane < 2) {
        b_r = bhh[0 * HH + (int)c * DPC + d];
        b_z = bhh[1 * HH + (int)c * DPC + d];
        b_n = bhh[2 * HH + (int)c * DPC + d];
        const int gb = (int)c * DPC + d;
        gi_r = __ldcg(&g_gi[gb]);
        gi_z = __ldcg(&g_gi[gb + HH]);
        gi_n = __ldcg(&g_gi[gb + 2 * HH]);
    }
    float h_own = 0.f;
    __syncthreads();
    cluster_sync_();   // mbarriers + zeroed hbuf visible before any st.async

    const unsigned hb_base = smem_u32(hbuf);

    for (int t = 0; t < TT; t++) {
        const int wsl = t & 3, psl = (t + 3) & 3;
        if (t > 0) mbar_wait(MB_FULL(psl), (unsigned)((t - 1) >> 2) & 1u);
        if (tid == 0) mbar_expect(MB_FULL(wsl), 2048u);

        // prefetch gi for t+1
        float ngr = 0.f, ngz = 0.f, ngn = 0.f;
        if (lane < 2) {
            const int tn = (t + 1 < TT) ? t + 1 : TT - 1;
            const size_t gb = (size_t)tn * G3 + (int)c * DPC + d;
            ngr = __ldcg(&g_gi[gb]);
            ngz = __ldcg(&g_gi[gb + HH]);
            ngn = __ldcg(&g_gi[gb + 2 * HH]);
        }

        // 6 dot products over h(t-1)
        unsigned long long acc[6];
#pragma unroll
        for (int r = 0; r < 6; r++) acc[r] = 0ull;
        const unsigned long long* h2 = (const unsigned long long*)(hbuf + psl * 512);
#pragma unroll
        for (int j = 0; j < 8; j++) {
            const unsigned long long hv = h2[lane + 32 * j];
#pragma unroll
            for (int r = 0; r < 6; r++)
                asm("fma.rn.f32x2 %0, %1, %2, %0;" : "+l"(acc[r]) : "l"(w[r][j]), "l"(hv));
        }
        float sum_r, sum_z, sum_n;
        {
            float lo, hi, f0, f1;
            asm("mov.b64 {%0, %1}, %2;" : "=f"(lo), "=f"(hi) : "l"(acc[0]));
            f0 = warp_sum(lo + hi);
            asm("mov.b64 {%0, %1}, %2;" : "=f"(lo), "=f"(hi) : "l"(acc[1]));
            f1 = warp_sum(lo + hi);
            sum_r = (lane & 1) ? f1 : f0;
            asm("mov.b64 {%0, %1}, %2;" : "=f"(lo), "=f"(hi) : "l"(acc[2]));
            f0 = warp_sum(lo + hi);
            asm("mov.b64 {%0, %1}, %2;" : "=f"(lo), "=f"(hi) : "l"(acc[3]));
            f1 = warp_sum(lo + hi);
            sum_z = (lane & 1) ? f1 : f0;
            asm("mov.b64 {%0, %1}, %2;" : "=f"(lo), "=f"(hi) : "l"(acc[4]));
            f0 = warp_sum(lo + hi);
            asm("mov.b64 {%0, %1}, %2;" : "=f"(lo), "=f"(hi) : "l"(acc[5]));
            f1 = warp_sum(lo + hi);
            sum_n = (lane & 1) ? f1 : f0;
        }

        // gates (valid in lanes 0,1; computed everywhere, harmless)
        const float rg = fast_sig(gi_r + sum_r + b_r);
        const float zg = fast_sig(gi_z + sum_z + b_z);
        const float ng = fast_tanh(gi_n + rg * (sum_n + b_n));
        const float hn = (1.f - zg) * ng + zg * h_own;
        if (lane < 2) {
            h_own = hn;
            hist[t * HSTR + d] = hn;
        }
        gi_r = ngr; gi_z = ngz; gi_n = ngn;

        // broadcast: lanes 0-15 ship dim 2w -> ranks 0-15; lanes 16-31 ship dim 2w+1
        const float bv = __shfl_sync(0xffffffffu, hn, lane >> 4);
        const unsigned dst = hb_base +
            (unsigned)((wsl * 512 + (int)c * DPC + 2 * warp + (lane >> 4)) * 4);
        st_async_f32(dst, MB_FULL(wsl), (unsigned)(lane & 15), bv);
    }
    // drain: all inbound stores for step 511 (slot 3, parity (511>>2)&1 = 1)
    mbar_wait(MB_FULL(3), 1u);
    __syncthreads();

    // ---- fused epilogue ----
    {   // partial scores: thread tid handles timestep tid
        float a = 0.f;
#pragma unroll 8
        for (int m = 0; m < 32; m++) a = fmaf(hist[tid * HSTR + m], qv[m], a);
        scp[tid] = a;
    }
    __syncthreads();
    {   // ship partials to rank 0
        const unsigned paddr = smem_u32(part) + (unsigned)(((int)c * 512 + tid) * 4);
        st_dsmem(paddr, 0u, scp[tid]);
    }
    cluster_sync_();

    if (c == 0) {   // softmax on rank 0, broadcast attn
        const float lam = fmaxf(expf(loglam[0]), 1e-4f);
        float s = 0.f;
#pragma unroll
        for (int cc = 0; cc < CL; cc++) s += part[cc * 512 + tid];
        s -= lam * (float)(TT - 1 - tid);

        float m = s;
#pragma unroll
        for (int o = 16; o > 0; o >>= 1) m = fmaxf(m, __shfl_xor_sync(0xffffffffu, m, o));
        if (lane == 0) red[warp] = m;
        __syncthreads();
        if (tid < 16) {
            float x = red[tid];
#pragma unroll
            for (int o = 8; o > 0; o >>= 1) x = fmaxf(x, __shfl_xor_sync(0xffffu, x, o));
            if (tid == 0) red[0] = x;
        }
        __syncthreads();
        const float mx = red[0];
        const float e = expf(s - mx);
        float ssum = warp_sum(e);
        __syncthreads();
        if (lane == 0) red[warp] = ssum;
        __syncthreads();
        if (tid < 16) {
            float x = red[tid];
#pragma unroll
            for (int o = 8; o > 0; o >>= 1) x += __shfl_xor_sync(0xffffu, x, o);
            if (tid == 0) red[0] = x;
        }
        __syncthreads();
        const float a = e / red[0];
        attn[tid] = a;
        if (out_size >= 1024) out[HH + tid] = a;
        const unsigned aaddr = smem_u32(attn) + (unsigned)(tid * 4);
        for (unsigned rk = 1; rk < CL; rk++) st_dsmem(aaddr, rk, a);
    }
    cluster_sync_();

    // summary for this CTA's 32 dims: warp g sums timesteps [32g, 32g+32), lane=dim
    {
        const int dd = tid & 31, g = tid >> 5;
        float a = 0.f;
#pragma unroll 4
        for (int i = 0; i < 32; i++) {
            const int t = g * 32 + i;
            a = fmaf(attn[t], hist[t * HSTR + dd], a);
        }
        scp[g * 32 + dd] = a;
    }
    __syncthreads();
    if (tid < 32) {
        float s = 0.f;
#pragma unroll
        for (int g = 0; g < 16; g++) s += scp[g * 32 + tid];
        const int o = (int)c * DPC + tid;
        if (o < out_size) out[o] = s;
    }
    cluster_sync_();   // no CTA exits with peer traffic in flight
}

// ---------------------------------------------------------------- launch
extern "C" void kernel_launch(void* const* d_in, const int* in_sizes, int n_in,
                              void* d_out, int out_size) {
    const int*   idx = (const int*)  d_in[0];
    const float* tf  = (const float*)d_in[1];
    const float* emb = (const float*)d_in[2];
    const float* ll  = (const float*)d_in[3];
    const float* lnw = (const float*)d_in[4];
    const float* lnb = (const float*)d_in[5];
    const float* w1  = (const float*)d_in[6];
    const float* b1  = (const float*)d_in[7];
    const float* w2  = (const float*)d_in[8];
    const float* b2  = (const float*)d_in[9];
    const float* wih = (const float*)d_in[10];
    const float* whh = (const float*)d_in[11];
    const float* bih = (const float*)d_in[12];
    const float* bhh = (const float*)d_in[13];
    const float* q   = (const float*)d_in[14];
    const float* llm = (const float*)d_in[15];
    float* out = (float*)d_out;

    const int k3_smem = 28224 * (int)sizeof(float);   // 112896 B dynamic

    static int attr_done = 0;
    if (!attr_done) {
        cudaFuncSetAttribute(k3_gru, cudaFuncAttributeNonPortableClusterSizeAllowed, 1);
        cudaFuncSetAttribute(k3_gru, cudaFuncAttributeMaxDynamicSharedMemorySize, k3_smem);
        attr_done = 1;
    }

    k1a<<<dim3(64, 2), 256>>>(idx, tf, emb, ll, lnw, lnb, w1, b1);
    k1b<<<64, 256>>>(w2, b2);
    k2_gi<<<dim3(64, 6), 256>>>(wih, bih);
    k3_gru<<<CL, 512, k3_smem>>>(whh, bhh, q, llm, out, out_size);
}

// round 7
// speedup vs baseline: 1.4595x; 1.4595x over previous
#include <cuda_runtime.h>
#include <math.h>

#define TT    512
#define DPOI  256
#define DIN   260
#define DHID  356
#define G3    1536
#define HH    512
#define CL    16          // cluster size
#define DPC   32          // h-dims per CTA
#define RPC   96          // rows per CTA
#define HSTR  33          // hist stride (bank-conflict pad)

__device__ float g_x  [TT * DPOI];
__device__ float g_hid[TT * DHID];
__device__ float g_gi [TT * G3];

__device__ __forceinline__ float warp_sum(float v) {
#pragma unroll
    for (int o = 16; o > 0; o >>= 1) v += __shfl_xor_sync(0xffffffffu, v, o);
    return v;
}
__device__ __forceinline__ unsigned smem_u32(const void* p) {
    unsigned a;
    asm("{ .reg .u64 t; cvta.to.shared.u64 t, %1; cvt.u32.u64 %0, t; }" : "=r"(a) : "l"(p));
    return a;
}
__device__ __forceinline__ void st_dsmem(unsigned addr, unsigned rank, float v) {
    unsigned ra;
    asm volatile("mapa.shared::cluster.u32 %0, %1, %2;" : "=r"(ra) : "r"(addr), "r"(rank));
    asm volatile("st.shared::cluster.f32 [%0], %1;" :: "r"(ra), "f"(v) : "memory");
}
__device__ __forceinline__ void cluster_sync_() {
    asm volatile("barrier.cluster.arrive.aligned;" ::: "memory");
    asm volatile("barrier.cluster.wait.aligned;"   ::: "memory");
}
__device__ __forceinline__ void mbar_init(unsigned a, unsigned cnt) {
    asm volatile("mbarrier.init.shared.b64 [%0], %1;" :: "r"(a), "r"(cnt) : "memory");
}
__device__ __forceinline__ void mbar_expect(unsigned a, unsigned tx) {
    asm volatile("mbarrier.arrive.expect_tx.shared.b64 _, [%0], %1;" :: "r"(a), "r"(tx) : "memory");
}
__device__ __forceinline__ void mbar_wait(unsigned a, unsigned parity) {
    unsigned done;
    asm volatile(
        "{\n\t.reg .pred p;\n\t"
        "mbarrier.try_wait.parity.acquire.cta.shared::cta.b64 p, [%1], %2;\n\t"
        "selp.b32 %0, 1, 0, p;\n\t}"
        : "=r"(done) : "r"(a), "r"(parity) : "memory");
    if (!done) {
        asm volatile(
            "{\n\t.reg .pred P1;\n\t"
            "W_%=:\n\t"
            "mbarrier.try_wait.parity.acquire.cta.shared::cta.b64 P1, [%0], %1;\n\t"
            "@P1 bra.uni D_%=;\n\t"
            "bra.uni W_%=;\n\t"
            "D_%=:\n\t}"
            :: "r"(a), "r"(parity) : "memory");
    }
}
__device__ __forceinline__ void st_async_f32(unsigned dst, unsigned bar, unsigned rk, float v) {
    unsigned rd, rb;
    asm volatile("mapa.shared::cluster.u32 %0, %1, %2;" : "=r"(rd) : "r"(dst), "r"(rk));
    asm volatile("mapa.shared::cluster.u32 %0, %1, %2;" : "=r"(rb) : "r"(bar), "r"(rk));
    asm volatile("st.async.shared::cluster.mbarrier::complete_tx::bytes.b32 [%0], %1, [%2];"
                 :: "r"(rd), "r"(__float_as_uint(v)), "r"(rb) : "memory");
}
__device__ __forceinline__ float fast_sig(float x) {
    return __fdividef(1.f, 1.f + __expf(-x));
}
__device__ __forceinline__ float fast_tanh(float x) {
    return 2.f * __fdividef(1.f, 1.f + __expf(-2.f * x)) - 1.f;
}

// ---------------------------------------------------------------- K1a: gather+feat+LN + W1/GELU
__global__ __launch_bounds__(256) void k1a(
    const int* __restrict__ idx, const float* __restrict__ tf,
    const float* __restrict__ emb, const float* __restrict__ ll,
    const float* __restrict__ lnw, const float* __restrict__ lnb,
    const float* __restrict__ w1, const float* __restrict__ b1)
{
    __shared__ float xs[8 * DIN];
    const int tid = threadIdx.x, warp = tid >> 5, lane = tid & 31;
    const int t0 = blockIdx.x * 8;
    const int hbase = blockIdx.y * 178;

    {   // one warp per timestep: gather + features + LayerNorm
        const int t = t0 + warp;
        const int pid = idx[t];
        const float4* er = (const float4*)(emb + (size_t)pid * DPOI);
        *(float4*)(xs + warp * DIN + 4 * lane)       = er[lane];
        *(float4*)(xs + warp * DIN + 128 + 4 * lane) = er[lane + 32];
        if (lane == 0) {
            float tc = fminf(fmaxf(tf[t], 0.f), 1.f);
            float s, c; sincosf(6.283185307179586f * tc, &s, &c);
            float f2 = 0.f, f3 = 0.f;
            if (t > 0) {
                float tp = fminf(fmaxf(tf[t - 1], 0.f), 1.f);
                float d = tc - tp;
                float m = d - floorf(d);
                f2 = log1pf(m * 24.f);
                const int ia = idx[t - 1];
                const float R = 0.017453292519943295f;
                float la1 = R * fminf(fmaxf(ll[2 * ia  + 0],  -90.f),  90.f);
                float lo1 = R * fminf(fmaxf(ll[2 * ia  + 1], -180.f), 180.f);
                float la2 = R * fminf(fmaxf(ll[2 * pid + 0],  -90.f),  90.f);
                float lo2 = R * fminf(fmaxf(ll[2 * pid + 1], -180.f), 180.f);
                float sa = sinf((la2 - la1) * 0.5f);
                float sb = sinf((lo2 - lo1) * 0.5f);
                float a = sa * sa + cosf(la1) * cosf(la2) * sb * sb;
                a = fminf(fmaxf(a, 0.f), 1.f);
                float cc = 2.f * atan2f(sqrtf(a), sqrtf(fmaxf(1.f - a, 1e-12f)));
                f3 = log1pf(6371.0088f * cc);
            }
            xs[warp * DIN + 256] = s;  xs[warp * DIN + 257] = c;
            xs[warp * DIN + 258] = f2; xs[warp * DIN + 259] = f3;
        }
        __syncwarp();
        float sm = 0.f, s2 = 0.f;
        for (int k = lane; k < DIN; k += 32) { float v = xs[warp * DIN + k]; sm += v; s2 += v * v; }
        sm = warp_sum(sm); s2 = warp_sum(s2);
        const float mu = sm * (1.f / DIN);
        const float inv = rsqrtf(s2 * (1.f / DIN) - mu * mu + 1e-5f);
        for (int k = lane; k < DIN; k += 32) {
            float v = xs[warp * DIN + k];
            xs[warp * DIN + k] = (v - mu) * inv * __ldg(&lnw[k]) + __ldg(&lnb[k]);
        }
    }
    __syncthreads();

    if (tid < 178) {
        const int h = hbase + tid;
        float acc[8];
#pragma unroll
        for (int i = 0; i < 8; i++) acc[i] = 0.f;
#pragma unroll 4
        for (int k = 0; k < DIN; k++) {
            const float wv = __ldg(&w1[k * DHID + h]);
#pragma unroll
            for (int i = 0; i < 8; i++) acc[i] = fmaf(xs[i * DIN + k], wv, acc[i]);
        }
        const float bb = __ldg(&b1[h]);
#pragma unroll
        for (int i = 0; i < 8; i++) {
            float v = acc[i] + bb;
            g_hid[(t0 + i) * DHID + h] = 0.5f * v * (1.f + erff(v * 0.7071067811865475f));
        }
    }
}

// ---------------------------------------------------------------- K1b: x = hid @ W2 + b2
__global__ __launch_bounds__(256) void k1b(
    const float* __restrict__ w2, const float* __restrict__ b2)
{
    __shared__ float hb[8 * DHID];
    const int tid = threadIdx.x;
    const int t0 = blockIdx.x * 8;

    for (int i = tid; i < 8 * DHID; i += 256) hb[i] = g_hid[t0 * DHID + i];
    __syncthreads();

    float acc[8];
#pragma unroll
    for (int i = 0; i < 8; i++) acc[i] = 0.f;
#pragma unroll 4
    for (int k = 0; k < DHID; k++) {
        const float wv = __ldg(&w2[k * DPOI + tid]);
#pragma unroll
        for (int i = 0; i < 8; i++) acc[i] = fmaf(hb[i * DHID + k], wv, acc[i]);
    }
    const float bo = __ldg(&b2[tid]);
#pragma unroll
    for (int i = 0; i < 8; i++) g_x[(t0 + i) * DPOI + tid] = acc[i] + bo;
}

// ---------------------------------------------------------------- K2: gi = x @ W_ih^T + bias
// bias = b_ih + b_hh for r,z rows (exact fold); b_ih only for n rows.
__global__ __launch_bounds__(256) void k2_gi(
    const float* __restrict__ wih, const float* __restrict__ bih,
    const float* __restrict__ bhh)
{
    __shared__ float xsm[8 * DPOI];
    __shared__ float wsmT[16 * 257];
    const int tid = threadIdx.x;
    const int t0 = blockIdx.x * 8;
    const int g0 = blockIdx.y * 256;

    for (int i = tid; i < 8 * DPOI; i += 256) xsm[i] = g_x[t0 * DPOI + i];

    float acc[8];
#pragma unroll
    for (int i = 0; i < 8; i++) acc[i] = 0.f;

    for (int k0 = 0; k0 < DPOI; k0 += 16) {
        __syncthreads();
        for (int i = tid; i < 4096; i += 256) {
            const int kk = i & 15, g = i >> 4;
            wsmT[kk * 257 + g] = wih[(size_t)(g0 + g) * DPOI + k0 + kk];
        }
        __syncthreads();
#pragma unroll
        for (int k4 = 0; k4 < 4; k4++) {
            float4 xv[8];
#pragma unroll
            for (int i = 0; i < 8; i++) xv[i] = *(const float4*)(xsm + i * DPOI + k0 + 4 * k4);
#pragma unroll
            for (int c = 0; c < 4; c++) {
                const float w = wsmT[(4 * k4 + c) * 257 + tid];
#pragma unroll
                for (int i = 0; i < 8; i++) {
                    float xk = (c == 0) ? xv[i].x : (c == 1) ? xv[i].y : (c == 2) ? xv[i].z : xv[i].w;
                    acc[i] = fmaf(xk, w, acc[i]);
                }
            }
        }
    }
    const int g = g0 + tid;
    float b = __ldg(&bih[g]);
    if (g < 2 * HH) b += __ldg(&bhh[g]);   // fold r,z hidden biases
#pragma unroll
    for (int i = 0; i < 8; i++) g_gi[(size_t)(t0 + i) * G3 + g] = acc[i] + b;
}

// ---------------------------------------------------------------- K3: GRU scan + fused epilogue
// 16-CTA cluster, 4-slot mbarrier pipeline. Warp w holds 6 W_hh rows in regs
// (gates r/z/n for dims 2w, 2w+1); sums go to smem; gate warp (tid<32)
// computes gates with MUFU math and broadcasts via st.async.
__global__ void __launch_bounds__(512, 1) __cluster_dims__(CL, 1, 1)
k3_gru(const float* __restrict__ whh, const float* __restrict__ bhh,
       const float* __restrict__ gq, const float* __restrict__ loglam,
       float* __restrict__ out, int out_size)
{
    extern __shared__ float sm[];
    float* hbuf = sm;                    // 4*512
    float* hist = sm + 2048;             // 512*33
    float* part = sm + 18944;            // 16*512
    float* attn = sm + 27136;            // 512
    float* scp  = sm + 27648;            // 512
    float* ghs  = sm + 28160;            // 96
    float* gis  = sm + 28256;            // 96
    float* bsn  = sm + 28352;            // 32 (n-gate hidden bias)
    float* qv   = sm + 28384;            // 32
    float* red  = sm + 28416;            // 16
    const unsigned mb = smem_u32(sm + 28432);   // 4 mbarriers
#define MB_FULL(s) (mb + (unsigned)((s) * 8))

    const int tid = threadIdx.x, warp = tid >> 5, lane = tid & 31;
    unsigned c; asm("mov.u32 %0, %%cluster_ctarank;" : "=r"(c));

    if (tid == 0) {
#pragma unroll
        for (int s = 0; s < 4; s++) mbar_init(MB_FULL(s), 1);
    }
    for (int i = tid; i < 2048; i += 512) hbuf[i] = 0.f;
    if (tid < 32) {
        qv[tid]  = gq[(int)c * DPC + tid] * rsqrtf((float)HH);
        bsn[tid] = bhh[2 * HH + (int)c * DPC + tid];
    }

    // resident rows: warp w, r=0..5 -> gate (r>>1), dim 2w + (r&1)
    unsigned long long w[6][8];
#pragma unroll
    for (int r = 0; r < 6; r++) {
        const int grow = (r >> 1) * HH + (int)c * DPC + 2 * warp + (r & 1);
        const unsigned long long* wp = (const unsigned long long*)(whh + (size_t)grow * HH);
#pragma unroll
        for (int j = 0; j < 8; j++) w[r][j] = wp[lane + 32 * j];
    }
    const int my_grow = (tid < RPC) ? ((tid >> 5) * HH + (int)c * DPC + (tid & 31)) : 0;
    __syncthreads();
    cluster_sync_();

    const unsigned hb_base = smem_u32(hbuf);

    for (int t = 0; t < TT; t++) {
        const int wsl = t & 3, psl = (t + 3) & 3;
        if (t > 0) mbar_wait(MB_FULL(psl), (unsigned)((t - 1) >> 2) & 1u);
        if (tid == 0) mbar_expect(MB_FULL(wsl), 2048u);

        float gval = 0.f;
        if (tid < RPC) gval = __ldcg(&g_gi[(size_t)t * G3 + my_grow]);

        // 6 dots over h(t-1)
        unsigned long long acc[6];
#pragma unroll
        for (int r = 0; r < 6; r++) acc[r] = 0ull;
        const unsigned long long* h2 = (const unsigned long long*)(hbuf + psl * 512);
#pragma unroll
        for (int j = 0; j < 8; j++) {
            const unsigned long long hv = h2[lane + 32 * j];
#pragma unroll
            for (int r = 0; r < 6; r++)
                asm("fma.rn.f32x2 %0, %1, %2, %0;" : "+l"(acc[r]) : "l"(w[r][j]), "l"(hv));
        }
        // paired reduction: 3 chains; even lane -> dim 2w sum, odd lane -> dim 2w+1
#pragma unroll
        for (int g = 0; g < 3; g++) {
            float lo, hi;
            asm("mov.b64 {%0, %1}, %2;" : "=f"(lo), "=f"(hi) : "l"(acc[2 * g]));
            const float ae = lo + hi;
            asm("mov.b64 {%0, %1}, %2;" : "=f"(lo), "=f"(hi) : "l"(acc[2 * g + 1]));
            const float ao = lo + hi;
            const float zv  = (lane & 1) ? ae : ao;
            float v = ((lane & 1) ? ao : ae) + __shfl_xor_sync(0xffffffffu, zv, 1);
#pragma unroll
            for (int o = 2; o <= 16; o <<= 1) v += __shfl_xor_sync(0xffffffffu, v, o);
            if (lane < 2) ghs[g * 32 + 2 * warp + lane] = v;
        }
        if (tid < RPC) gis[tid] = gval;
        __syncthreads();

        // gate warp: fast gates + broadcast
        if (tid < 32) {
            const int m = tid;
            const float rg = fast_sig(gis[m]      + ghs[m]);
            const float zg = fast_sig(gis[32 + m] + ghs[32 + m]);
            const float ng = fast_tanh(gis[64 + m] + rg * (ghs[64 + m] + bsn[m]));
            const float hn = (1.f - zg) * ng + zg * hbuf[psl * 512 + (int)c * DPC + m];
            hist[t * HSTR + m] = hn;
            const unsigned dst = hb_base + (unsigned)((wsl * 512 + (int)c * DPC + m) * 4);
            const unsigned bar = MB_FULL(wsl);
#pragma unroll
            for (unsigned rk = 0; rk < CL; rk++) st_async_f32(dst, bar, rk, hn);
        }
    }
    mbar_wait(MB_FULL(3), 1u);   // drain final slot
    __syncthreads();

    // ---- fused epilogue ----
    {   // partial scores: thread tid = timestep tid over this CTA's 32 dims
        float a = 0.f;
#pragma unroll 8
        for (int m = 0; m < 32; m++) a = fmaf(hist[tid * HSTR + m], qv[m], a);
        scp[tid] = a;
    }
    __syncthreads();
    {   // ship partials to rank 0
        const unsigned paddr = smem_u32(part) + (unsigned)(((int)c * 512 + tid) * 4);
        st_dsmem(paddr, 0u, scp[tid]);
    }
    cluster_sync_();

    if (c == 0) {
        const float lam = fmaxf(expf(loglam[0]), 1e-4f);
        float s = 0.f;
#pragma unroll
        for (int cc = 0; cc < CL; cc++) s += part[cc * 512 + tid];
        s -= lam * (float)(TT - 1 - tid);

        float m = s;
#pragma unroll
        for (int o = 16; o > 0; o >>= 1) m = fmaxf(m, __shfl_xor_sync(0xffffffffu, m, o));
        if (lane == 0) red[warp] = m;
        __syncthreads();
        if (tid < 16) {
            float x = red[tid];
#pragma unroll
            for (int o = 8; o > 0; o >>= 1) x = fmaxf(x, __shfl_xor_sync(0xffffu, x, o));
            if (tid == 0) red[0] = x;
        }
        __syncthreads();
        const float mx = red[0];
        const float e = expf(s - mx);
        float ssum = warp_sum(e);
        __syncthreads();
        if (lane == 0) red[warp] = ssum;
        __syncthreads();
        if (tid < 16) {
            float x = red[tid];
#pragma unroll
            for (int o = 8; o > 0; o >>= 1) x += __shfl_xor_sync(0xffffu, x, o);
            if (tid == 0) red[0] = x;
        }
        __syncthreads();
        const float a = e / red[0];
        attn[tid] = a;
        if (out_size >= 1024) out[HH + tid] = a;
        const unsigned aaddr = smem_u32(attn) + (unsigned)(tid * 4);
        for (unsigned rk = 1; rk < CL; rk++) st_dsmem(aaddr, rk, a);
    }
    cluster_sync_();

    {   // summary: warp g sums timesteps [32g,32g+32), lane = dim
        const int dd = tid & 31, g = tid >> 5;
        float a = 0.f;
#pragma unroll 4
        for (int i = 0; i < 32; i++) {
            const int t = g * 32 + i;
            a = fmaf(attn[t], hist[t * HSTR + dd], a);
        }
        scp[g * 32 + dd] = a;
    }
    __syncthreads();
    if (tid < 32) {
        float s = 0.f;
#pragma unroll
        for (int g = 0; g < 16; g++) s += scp[g * 32 + tid];
        const int o = (int)c * DPC + tid;
        if (o < out_size) out[o] = s;
    }
    cluster_sync_();
}

// ---------------------------------------------------------------- launch
extern "C" void kernel_launch(void* const* d_in, const int* in_sizes, int n_in,
                              void* d_out, int out_size) {
    const int*   idx = (const int*)  d_in[0];
    const float* tf  = (const float*)d_in[1];
    const float* emb = (const float*)d_in[2];
    const float* ll  = (const float*)d_in[3];
    const float* lnw = (const float*)d_in[4];
    const float* lnb = (const float*)d_in[5];
    const float* w1  = (const float*)d_in[6];
    const float* b1  = (const float*)d_in[7];
    const float* w2  = (const float*)d_in[8];
    const float* b2  = (const float*)d_in[9];
    const float* wih = (const float*)d_in[10];
    const float* whh = (const float*)d_in[11];
    const float* bih = (const float*)d_in[12];
    const float* bhh = (const float*)d_in[13];
    const float* q   = (const float*)d_in[14];
    const float* llm = (const float*)d_in[15];
    float* out = (float*)d_out;

    const int k3_smem = 28448 * (int)sizeof(float);

    static int attr_done = 0;
    if (!attr_done) {
        cudaFuncSetAttribute(k3_gru, cudaFuncAttributeNonPortableClusterSizeAllowed, 1);
        cudaFuncSetAttribute(k3_gru, cudaFuncAttributeMaxDynamicSharedMemorySize, k3_smem);
        attr_done = 1;
    }

    k1a<<<dim3(64, 2), 256>>>(idx, tf, emb, ll, lnw, lnb, w1, b1);
    k1b<<<64, 256>>>(w2, b2);
    k2_gi<<<dim3(64, 6), 256>>>(wih, bih, bhh);
    k3_gru<<<CL, 512, k3_smem>>>(whh, bhh, q, llm, out, out_size);
}